// round 13
// baseline (speedup 1.0000x reference)
#include <cuda_runtime.h>
#include <cuda_fp16.h>
#include <cuda_bf16.h>

#define NN 100000
#define NE 1600000
#define NF 128
#define NH 64
#define NC 40
#define H2S 64        // padded h2 row: 64 halfs (128 B)

#define SCAN_B 1024
#define NBLK ((NN + SCAN_B - 1) / SCAN_B)   // 98

#define GR 256        // rows per gemm1 block
#define APAD 136      // bf16 row stride in smem
#define G1_SMEM ((GR + NH) * APAD * 2)   // 87040 B

#define G2R 128       // rows per gemm2 block
#define A2PAD 72      // half row stride (144 B)
#define G2_SMEM ((G2R + NC) * A2PAD * 2) // 24192 B

// ---------------- scratch ----------------
__device__ int                 g_src[NE];
__device__ int                 g_dst[NE];
__device__ unsigned short      g_rank[NE];      // edge's rank within its dst row
__device__ unsigned long long  g_pack[NN];      // (cnt<<40) | fixedpoint(sum w, 2^32); self-cleaned
__device__ int                 g_rowptr[NN + 1];
__device__ float               g_dinv[NN];
__device__ unsigned            g_edge[NE];      // CSR: (src<<15) | fp16bits(dinv_s*w)
__device__ __half2             g_h1h[NN * 32];  // h1 fp16 (128 B rows)
__device__ __half2             g_a1h[NN * 32];  // a1 fp16 (128 B rows)
__device__ __half              g_h2h[NN * H2S]; // h2 fp16 padded (128 B rows)
__device__ volatile unsigned long long g_sstat[NBLK];  // self-cleaned by k_fill

// ---------------- fused decode + packed degree/count + rank --------------------
__global__ void k_decode_deg(const void* __restrict__ ei, const float* __restrict__ w) {
    __shared__ int ok;
    int tid = threadIdx.x;
    if (tid == 0) ok = 1;
    __syncthreads();
    {   // per-block dtype detect: 256 leading int64 values must be in [0, NN)
        long long v = ((const long long*)ei)[tid & 255];
        if (!(v >= 0 && v < (long long)NN)) atomicAnd(&ok, 0);
    }
    __syncthreads();
    int e = blockIdx.x * blockDim.x + tid;
    if (e >= NE) return;
    int s, d;
    if (ok) {
        const long long* p = (const long long*)ei;
        s = (int)p[e]; d = (int)p[NE + e];
    } else {
        const int* p = (const int*)ei;
        s = p[e]; d = p[NE + e];
    }
    g_src[e] = s;
    g_dst[e] = d;
    unsigned long long add = (1ull << 40) |
        (unsigned long long)(w[e] * 4294967296.0f);
    unsigned long long old = atomicAdd(&g_pack[d], add);
    g_rank[e] = (unsigned short)(old >> 40);
}

// ---------------- single-pass scan (decoupled lookback) + dinv + self-clean ----
__global__ __launch_bounds__(SCAN_B) void k_scan() {
    int b = blockIdx.x, t = threadIdx.x;
    int gid = b * SCAN_B + t;
    unsigned long long pk = (gid < NN) ? g_pack[gid] : 0ull;
    int v = (int)(pk >> 40);

    int lane = t & 31, wid = t >> 5;
    int incl = v;
    #pragma unroll
    for (int o = 1; o < 32; o <<= 1) {
        int u = __shfl_up_sync(0xffffffffu, incl, o);
        if (lane >= o) incl += u;
    }
    __shared__ int ws[32];
    if (lane == 31) ws[wid] = incl;
    __syncthreads();
    if (wid == 0) {
        int s = ws[lane];
        #pragma unroll
        for (int o = 1; o < 32; o <<= 1) {
            int u = __shfl_up_sync(0xffffffffu, s, o);
            if (lane >= o) s += u;
        }
        ws[lane] = s;
    }
    __syncthreads();
    if (wid > 0) incl += ws[wid - 1];
    int total = ws[31];

    if (t == 0)
        atomicExch((unsigned long long*)&g_sstat[b],
                   (1ull << 63) | (unsigned long long)total);

    __shared__ int boff_s;
    if (wid == 0) {
        int run = 0;
        for (int i = lane; i < b; i += 32) {
            unsigned long long s;
            do { s = g_sstat[i]; } while (!(s >> 63));
            run += (int)(s & 0x7FFFFFFFFFFFFFFFull);
        }
        #pragma unroll
        for (int o = 16; o > 0; o >>= 1)
            run += __shfl_xor_sync(0xffffffffu, run, o);
        if (lane == 0) boff_s = run;
    }
    __syncthreads();

    if (gid < NN) {
        g_rowptr[gid] = boff_s + incl - v;   // exclusive prefix
        g_pack[gid]   = 0ull;                // self-clean for next replay
        float degw = (float)(pk & 0xFFFFFFFFFFull) * (1.0f / 4294967296.0f);
        g_dinv[gid] = rsqrtf(degw + 1.0f);
    }
    if (gid == NN) g_rowptr[NN] = boff_s + incl;   // total edge count
}

// ---------------- CSR fill: NO atomics (rank-based placement) ------------------
__global__ void k_fill(const float* __restrict__ w) {
    int e = blockIdx.x * blockDim.x + threadIdx.x;
    if (e < NBLK) g_sstat[e] = 0ull;     // self-clean scan status for next replay
    if (e >= NE) return;
    int s = g_src[e], d = g_dst[e];
    int pos = g_rowptr[d] + (int)g_rank[e];
    float nv = g_dinv[s] * w[e];
    unsigned hb = (unsigned)__half_as_ushort(__float2half(nv));
    g_edge[pos] = ((unsigned)s << 15) | (hb & 0x7FFFu);
}

// ---------------- mma / unpack helpers ----------------
__device__ __forceinline__ void mma16816bf(float* d,
                                           unsigned a0, unsigned a1, unsigned a2, unsigned a3,
                                           unsigned b0, unsigned b1) {
    asm volatile(
        "mma.sync.aligned.m16n8k16.row.col.f32.bf16.bf16.f32 "
        "{%0,%1,%2,%3}, {%4,%5,%6,%7}, {%8,%9}, {%0,%1,%2,%3};"
        : "+f"(d[0]), "+f"(d[1]), "+f"(d[2]), "+f"(d[3])
        : "r"(a0), "r"(a1), "r"(a2), "r"(a3), "r"(b0), "r"(b1));
}
__device__ __forceinline__ void mma16816h(float* d,
                                          unsigned a0, unsigned a1, unsigned a2, unsigned a3,
                                          unsigned b0, unsigned b1) {
    asm volatile(
        "mma.sync.aligned.m16n8k16.row.col.f32.f16.f16.f32 "
        "{%0,%1,%2,%3}, {%4,%5,%6,%7}, {%8,%9}, {%0,%1,%2,%3};"
        : "+f"(d[0]), "+f"(d[1]), "+f"(d[2]), "+f"(d[3])
        : "r"(a0), "r"(a1), "r"(a2), "r"(a3), "r"(b0), "r"(b1));
}
__device__ __forceinline__ void fma8(float* acc, uint4 v, float n) {
    float2 f0 = __half22float2(*(__half2*)&v.x);
    float2 f1 = __half22float2(*(__half2*)&v.y);
    float2 f2 = __half22float2(*(__half2*)&v.z);
    float2 f3 = __half22float2(*(__half2*)&v.w);
    acc[0] = fmaf(n, f0.x, acc[0]); acc[1] = fmaf(n, f0.y, acc[1]);
    acc[2] = fmaf(n, f1.x, acc[2]); acc[3] = fmaf(n, f1.y, acc[3]);
    acc[4] = fmaf(n, f2.x, acc[4]); acc[5] = fmaf(n, f2.y, acc[5]);
    acc[6] = fmaf(n, f3.x, acc[6]); acc[7] = fmaf(n, f3.y, acc[7]);
}
__device__ __forceinline__ float edge_norm(unsigned u) {
    return __half2float(__ushort_as_half((unsigned short)(u & 0x7FFFu)));
}

// ---------------- GEMM1: 512 thr, 16 warps x m16 -------------------------------
__global__ __launch_bounds__(512) void k_gemm1(const float* __restrict__ x,
                                               const float* __restrict__ W1) {
    extern __shared__ __nv_bfloat16 sh[];
    __nv_bfloat16* As = sh;                  // [GR][APAD]
    __nv_bfloat16* Ws = sh + GR * APAD;      // [NH][APAD]
    int tid = threadIdx.x;
    int row0 = blockIdx.x * GR;

    const float4* W4 = (const float4*)W1;
    for (int i = tid; i < (NF * NH) / 4; i += 512) {
        int idx = i * 4;
        int k = idx / NH;
        int n = idx % NH;
        float4 w = W4[i];
        Ws[(n + 0) * APAD + k] = __float2bfloat16(w.x);
        Ws[(n + 1) * APAD + k] = __float2bfloat16(w.y);
        Ws[(n + 2) * APAD + k] = __float2bfloat16(w.z);
        Ws[(n + 3) * APAD + k] = __float2bfloat16(w.w);
    }

    const float4* x4 = (const float4*)x;
    #pragma unroll
    for (int it = 0; it < GR * 32 / 512; it++) {
        int i  = tid + 512 * it;
        int r  = i >> 5;
        int c4 = i & 31;
        int gr = row0 + r;
        float4 v = (gr < NN) ? x4[(size_t)gr * 32 + c4] : make_float4(0.f, 0.f, 0.f, 0.f);
        __nv_bfloat162 p0 = __float22bfloat162_rn(make_float2(v.x, v.y));
        __nv_bfloat162 p1 = __float22bfloat162_rn(make_float2(v.z, v.w));
        *(__nv_bfloat162*)&As[r * APAD + c4 * 4]     = p0;
        *(__nv_bfloat162*)&As[r * APAD + c4 * 4 + 2] = p1;
    }
    __syncthreads();

    int w    = tid >> 5;
    int lane = tid & 31;
    int g    = lane >> 2;
    int tg   = lane & 3;
    int mrow0 = w * 16;

    float acc[8][4];
    #pragma unroll
    for (int nt = 0; nt < 8; nt++)
        #pragma unroll
        for (int c = 0; c < 4; c++) acc[nt][c] = 0.f;

    #pragma unroll
    for (int ks = 0; ks < NF / 16; ks++) {
        int k0 = ks * 16;
        unsigned a0 = *(const unsigned*)&As[(mrow0 + g)     * APAD + k0 + tg * 2];
        unsigned a1 = *(const unsigned*)&As[(mrow0 + g + 8) * APAD + k0 + tg * 2];
        unsigned a2 = *(const unsigned*)&As[(mrow0 + g)     * APAD + k0 + tg * 2 + 8];
        unsigned a3 = *(const unsigned*)&As[(mrow0 + g + 8) * APAD + k0 + tg * 2 + 8];
        #pragma unroll
        for (int nt = 0; nt < 8; nt++) {
            unsigned b0 = *(const unsigned*)&Ws[(nt * 8 + g) * APAD + k0 + tg * 2];
            unsigned b1 = *(const unsigned*)&Ws[(nt * 8 + g) * APAD + k0 + tg * 2 + 8];
            mma16816bf(acc[nt], a0, a1, a2, a3, b0, b1);
        }
    }

    int rA = row0 + mrow0 + g;
    int rB = rA + 8;
    #pragma unroll
    for (int nt = 0; nt < 8; nt++) {
        int colh2 = nt * 4 + tg;
        if (rA < NN)
            g_h1h[(size_t)rA * 32 + colh2] = __floats2half2_rn(acc[nt][0], acc[nt][1]);
        if (rB < NN)
            g_h1h[(size_t)rB * 32 + colh2] = __floats2half2_rn(acc[nt][2], acc[nt][3]);
    }
}

// ---------------- AGG1: 8-lane-group vector gather + bias + relu ----------------
__global__ __launch_bounds__(256) void k_agg1(const float* __restrict__ b1) {
    int node = (blockIdx.x * blockDim.x + threadIdx.x) >> 5;
    int lane = threadIdx.x & 31;
    if (node >= NN) return;
    int beg = g_rowptr[node];
    int end = g_rowptr[node + 1];
    float di = g_dinv[node];
    int g8 = lane >> 3;
    int fc = lane & 7;

    const uint4* h4 = (const uint4*)g_h1h;
    float acc[8];
    #pragma unroll
    for (int j = 0; j < 8; j++) acc[j] = 0.f;
    if (g8 == 0) {
        uint4 sv = h4[(size_t)node * 8 + fc];
        fma8(acc, sv, di);
    }

    int e = beg;
    for (; e + 7 < end; e += 8) {
        unsigned u0 = g_edge[e + g8];
        unsigned u1 = g_edge[e + 4 + g8];
        int s0 = (int)(u0 >> 15), s1 = (int)(u1 >> 15);
        uint4 v0 = h4[(size_t)s0 * 8 + fc];
        uint4 v1 = h4[(size_t)s1 * 8 + fc];
        fma8(acc, v0, edge_norm(u0));
        fma8(acc, v1, edge_norm(u1));
    }
    for (; e < end; e += 4) {
        int ee = e + g8;
        float n = 0.f;
        int s = 0;
        if (ee < end) {
            unsigned u = g_edge[ee];
            s = (int)(u >> 15);
            n = edge_norm(u);
        }
        uint4 v = h4[(size_t)s * 8 + fc];
        fma8(acc, v, n);
    }

    #pragma unroll
    for (int j = 0; j < 8; j++) {
        acc[j] += __shfl_xor_sync(0xffffffffu, acc[j], 8);
        acc[j] += __shfl_xor_sync(0xffffffffu, acc[j], 16);
    }

    if (g8 == 0) {
        float4 bA = *(const float4*)&b1[fc * 8];
        float4 bB = *(const float4*)&b1[fc * 8 + 4];
        float r0 = fmaxf(fmaf(di, acc[0], bA.x), 0.f);
        float r1 = fmaxf(fmaf(di, acc[1], bA.y), 0.f);
        float r2 = fmaxf(fmaf(di, acc[2], bA.z), 0.f);
        float r3 = fmaxf(fmaf(di, acc[3], bA.w), 0.f);
        float r4 = fmaxf(fmaf(di, acc[4], bB.x), 0.f);
        float r5 = fmaxf(fmaf(di, acc[5], bB.y), 0.f);
        float r6 = fmaxf(fmaf(di, acc[6], bB.z), 0.f);
        float r7 = fmaxf(fmaf(di, acc[7], bB.w), 0.f);
        uint4 st;
        __half2 h0 = __floats2half2_rn(r0, r1);
        __half2 h1 = __floats2half2_rn(r2, r3);
        __half2 h2 = __floats2half2_rn(r4, r5);
        __half2 h3 = __floats2half2_rn(r6, r7);
        st.x = *(unsigned*)&h0; st.y = *(unsigned*)&h1;
        st.z = *(unsigned*)&h2; st.w = *(unsigned*)&h3;
        ((uint4*)g_a1h)[(size_t)node * 8 + fc] = st;
    }
}

// ---------------- GEMM2: h2 = a1 @ W2 (padded fp16 rows) ------------------------
__global__ __launch_bounds__(256) void k_gemm2(const float* __restrict__ W2) {
    extern __shared__ __half sh2[];
    __half* As = sh2;                    // [G2R][A2PAD]
    __half* Ws = sh2 + G2R * A2PAD;      // [NC][A2PAD]
    int tid = threadIdx.x;
    int row0 = blockIdx.x * G2R;

    for (int i = tid; i < NH * NC; i += 256) {
        int k = i / NC, n = i % NC;
        Ws[n * A2PAD + k] = __float2half(W2[i]);
    }
    const uint4* a4 = (const uint4*)g_a1h;
    #pragma unroll
    for (int it = 0; it < G2R * 8 / 256; it++) {
        int i = tid + 256 * it;
        int r = i >> 3;
        int c = i & 7;
        int gr = row0 + r;
        uint4 v = (gr < NN) ? a4[(size_t)gr * 8 + c] : make_uint4(0u, 0u, 0u, 0u);
        *(uint4*)&As[r * A2PAD + c * 8] = v;
    }
    __syncthreads();

    int w    = tid >> 5;
    int lane = tid & 31;
    int g    = lane >> 2;
    int tg   = lane & 3;
    int mrow0 = w * 16;

    float acc[5][4];
    #pragma unroll
    for (int nt = 0; nt < 5; nt++)
        #pragma unroll
        for (int c = 0; c < 4; c++) acc[nt][c] = 0.f;

    #pragma unroll
    for (int ks = 0; ks < NH / 16; ks++) {
        int k0 = ks * 16;
        unsigned a0 = *(const unsigned*)&As[(mrow0 + g)     * A2PAD + k0 + tg * 2];
        unsigned a1 = *(const unsigned*)&As[(mrow0 + g + 8) * A2PAD + k0 + tg * 2];
        unsigned a2 = *(const unsigned*)&As[(mrow0 + g)     * A2PAD + k0 + tg * 2 + 8];
        unsigned a3 = *(const unsigned*)&As[(mrow0 + g + 8) * A2PAD + k0 + tg * 2 + 8];
        #pragma unroll
        for (int nt = 0; nt < 5; nt++) {
            unsigned b0 = *(const unsigned*)&Ws[(nt * 8 + g) * A2PAD + k0 + tg * 2];
            unsigned b1 = *(const unsigned*)&Ws[(nt * 8 + g) * A2PAD + k0 + tg * 2 + 8];
            mma16816h(acc[nt], a0, a1, a2, a3, b0, b1);
        }
    }

    int rA = row0 + mrow0 + g;
    int rB = rA + 8;
    #pragma unroll
    for (int nt = 0; nt < 5; nt++) {
        int col = nt * 8 + tg * 2;
        if (rA < NN)
            *(__half2*)&g_h2h[(size_t)rA * H2S + col] =
                __floats2half2_rn(acc[nt][0], acc[nt][1]);
        if (rB < NN)
            *(__half2*)&g_h2h[(size_t)rB * H2S + col] =
                __floats2half2_rn(acc[nt][2], acc[nt][3]);
    }
}

// ---------------- AGG2: 8-lane-group vector gather + bias + log_softmax ---------
__global__ __launch_bounds__(256) void k_agg2(const float* __restrict__ b2,
                                              float* __restrict__ out) {
    int node = (blockIdx.x * blockDim.x + threadIdx.x) >> 5;
    int lane = threadIdx.x & 31;
    if (node >= NN) return;
    int beg = g_rowptr[node];
    int end = g_rowptr[node + 1];
    float di = g_dinv[node];
    int g8 = lane >> 3;
    int fc = lane & 7;

    const uint4* h4 = (const uint4*)g_h2h;
    float acc[8];
    #pragma unroll
    for (int j = 0; j < 8; j++) acc[j] = 0.f;
    if (g8 == 0) {
        uint4 sv = h4[(size_t)node * 8 + fc];
        fma8(acc, sv, di);
    }

    int e = beg;
    for (; e + 7 < end; e += 8) {
        unsigned u0 = g_edge[e + g8];
        unsigned u1 = g_edge[e + 4 + g8];
        int s0 = (int)(u0 >> 15), s1 = (int)(u1 >> 15);
        uint4 v0 = h4[(size_t)s0 * 8 + fc];
        uint4 v1 = h4[(size_t)s1 * 8 + fc];
        fma8(acc, v0, edge_norm(u0));
        fma8(acc, v1, edge_norm(u1));
    }
    for (; e < end; e += 4) {
        int ee = e + g8;
        float n = 0.f;
        int s = 0;
        if (ee < end) {
            unsigned u = g_edge[ee];
            s = (int)(u >> 15);
            n = edge_norm(u);
        }
        uint4 v = h4[(size_t)s * 8 + fc];
        fma8(acc, v, n);
    }

    #pragma unroll
    for (int j = 0; j < 8; j++) {
        acc[j] += __shfl_xor_sync(0xffffffffu, acc[j], 8);
        acc[j] += __shfl_xor_sync(0xffffffffu, acc[j], 16);
    }

    float v[8];
    float mloc = -1e30f;
    if (fc < 5) {
        float4 bA = *(const float4*)&b2[fc * 8];
        float4 bB = *(const float4*)&b2[fc * 8 + 4];
        v[0] = fmaf(di, acc[0], bA.x); v[1] = fmaf(di, acc[1], bA.y);
        v[2] = fmaf(di, acc[2], bA.z); v[3] = fmaf(di, acc[3], bA.w);
        v[4] = fmaf(di, acc[4], bB.x); v[5] = fmaf(di, acc[5], bB.y);
        v[6] = fmaf(di, acc[6], bB.z); v[7] = fmaf(di, acc[7], bB.w);
        #pragma unroll
        for (int j = 0; j < 8; j++) mloc = fmaxf(mloc, v[j]);
    }
    #pragma unroll
    for (int off = 16; off > 0; off >>= 1)
        mloc = fmaxf(mloc, __shfl_xor_sync(0xffffffffu, mloc, off));

    float sloc = 0.f;
    if (fc < 5 && g8 == 0) {
        #pragma unroll
        for (int j = 0; j < 8; j++) sloc += __expf(v[j] - mloc);
    }
    #pragma unroll
    for (int off = 16; off > 0; off >>= 1)
        sloc += __shfl_xor_sync(0xffffffffu, sloc, off);
    float lse = mloc + __logf(sloc);

    if (fc < 5 && g8 == 0) {
        float* o = out + (size_t)node * NC + fc * 8;
        *(float4*)o       = make_float4(v[0] - lse, v[1] - lse, v[2] - lse, v[3] - lse);
        *(float4*)(o + 4) = make_float4(v[4] - lse, v[5] - lse, v[6] - lse, v[7] - lse);
    }
}

// ---------------- launcher (2-stream fork: gemm1 overlaps CSR build) -----------
extern "C" void kernel_launch(void* const* d_in, const int* in_sizes, int n_in,
                              void* d_out, int out_size) {
    const float* x  = (const float*)d_in[0];
    const void*  ei = d_in[1];
    const float* ew = (const float*)d_in[2];
    const float* W1 = (const float*)d_in[3];
    const float* b1 = (const float*)d_in[4];
    const float* W2 = (const float*)d_in[5];
    const float* b2 = (const float*)d_in[6];
    float* out = (float*)d_out;

    const int EB  = (NE + 255) / 256;       // 6250
    const int G1B = (NN + GR - 1) / GR;     // 391
    const int G2B = (NN + G2R - 1) / G2R;   // 782
    const int AB  = (NN * 32 + 255) / 256;  // 12500

    static cudaStream_t sA = nullptr;
    static cudaEvent_t evFork = nullptr, evG1 = nullptr;
    if (sA == nullptr) {
        cudaStreamCreateWithFlags(&sA, cudaStreamNonBlocking);
        cudaEventCreateWithFlags(&evFork, cudaEventDisableTiming);
        cudaEventCreateWithFlags(&evG1, cudaEventDisableTiming);
        cudaFuncSetAttribute(k_gemm1, cudaFuncAttributeMaxDynamicSharedMemorySize, G1_SMEM);
        cudaFuncSetAttribute(k_gemm2, cudaFuncAttributeMaxDynamicSharedMemorySize, G2_SMEM);
    }

    // fork: gemm1 depends only on inputs -> run on side stream
    cudaEventRecord(evFork, 0);
    cudaStreamWaitEvent(sA, evFork, 0);
    k_gemm1<<<G1B, 512, G1_SMEM, sA>>>(x, W1);
    cudaEventRecord(evG1, sA);

    // main stream: CSR build pipeline (self-cleaning state, no init kernel)
    k_decode_deg<<<EB, 256>>>(ei, ew);
    k_scan<<<NBLK, SCAN_B>>>();
    k_fill<<<EB, 256>>>(ew);

    // join: agg1 needs both h1 (sA) and CSR (stream 0)
    cudaStreamWaitEvent(0, evG1, 0);
    k_agg1<<<AB, 256>>>(b1);
    k_gemm2<<<G2B, 256, G2_SMEM>>>(W2);
    k_agg2<<<AB, 256>>>(b2, out);
}

// round 15
// speedup vs baseline: 1.0223x; 1.0223x over previous
#include <cuda_runtime.h>
#include <cuda_fp16.h>
#include <cuda_bf16.h>

#define NN 100000
#define NE 1600000
#define NF 128
#define NH 64
#define NC 40
#define H2S 64        // padded h2 row: 64 halfs (128 B)

#define SCAN_B 1024
#define NBLK ((NN + SCAN_B - 1) / SCAN_B)   // 98

#define GR 256        // rows per gemm1 block
#define APAD 136      // bf16 row stride in smem
#define G1_SMEM ((GR + NH) * APAD * 2)   // 87040 B

#define G2R 128       // rows per gemm2 block
#define A2PAD 72      // half row stride (144 B)
#define G2_SMEM ((G2R + NC) * A2PAD * 2) // 24192 B

// ---------------- scratch ----------------
__device__ int                 g_sd[2 * NE];    // interleaved {src,dst} per edge
__device__ unsigned short      g_rank[NE];      // edge's rank within its dst row
__device__ unsigned long long  g_pack[NN];      // (cnt<<40) | fixedpoint(sum w); self-cleaned
__device__ int                 g_rowptr[NN + 1];
__device__ float               g_dinv[NN];
__device__ unsigned            g_edge[NE];      // CSR: (src<<15) | fp16bits(w)
__device__ __half2             g_h1h[NN * 32];  // dinv-scaled h1 fp16 (128 B rows)
__device__ __half2             g_a1h[NN * 32];  // a1 fp16 (128 B rows)
__device__ __half              g_h2h[NN * H2S]; // dinv-scaled h2 fp16 padded (128 B rows)
__device__ volatile unsigned long long g_sstat[NBLK];  // self-cleaned by k_fill

// -------- decode (4 edges/thread, vectorized) + packed degree/count + rank -----
__global__ void k_decode_deg(const void* __restrict__ ei, const float* __restrict__ w) {
    __shared__ int ok;
    int tid = threadIdx.x;
    if (tid == 0) ok = 1;
    __syncthreads();
    {   // per-block dtype detect: 256 leading int64 values must be in [0, NN)
        long long v = ((const long long*)ei)[tid & 255];
        if (!(v >= 0 && v < (long long)NN)) atomicAnd(&ok, 0);
    }
    __syncthreads();
    int e0 = (blockIdx.x * blockDim.x + tid) * 4;
    if (e0 >= NE) return;

    int s[4], d[4];
    if (ok) {
        const long long* p = (const long long*)ei;
        longlong2 sa = *(const longlong2*)&p[e0];
        longlong2 sb = *(const longlong2*)&p[e0 + 2];
        longlong2 da = *(const longlong2*)&p[NE + e0];
        longlong2 db = *(const longlong2*)&p[NE + e0 + 2];
        s[0] = (int)sa.x; s[1] = (int)sa.y; s[2] = (int)sb.x; s[3] = (int)sb.y;
        d[0] = (int)da.x; d[1] = (int)da.y; d[2] = (int)db.x; d[3] = (int)db.y;
    } else {
        const int* p = (const int*)ei;
        int4 sa = *(const int4*)&p[e0];
        int4 da = *(const int4*)&p[NE + e0];
        s[0] = sa.x; s[1] = sa.y; s[2] = sa.z; s[3] = sa.w;
        d[0] = da.x; d[1] = da.y; d[2] = da.z; d[3] = da.w;
    }
    float4 wv = *(const float4*)&w[e0];
    float wa[4] = {wv.x, wv.y, wv.z, wv.w};
    unsigned short rk[4];
    #pragma unroll
    for (int j = 0; j < 4; j++) {
        unsigned long long add = (1ull << 40) |
            (unsigned long long)(wa[j] * 4294967296.0f);
        unsigned long long old = atomicAdd(&g_pack[d[j]], add);
        rk[j] = (unsigned short)(old >> 40);
    }
    ((int4*)g_sd)[(e0 >> 1)    ] = make_int4(s[0], d[0], s[1], d[1]);
    ((int4*)g_sd)[(e0 >> 1) + 1] = make_int4(s[2], d[2], s[3], d[3]);
    *(ushort4*)&g_rank[e0] = make_ushort4(rk[0], rk[1], rk[2], rk[3]);
}

// ---------------- single-pass scan (decoupled lookback) + dinv + self-clean ----
__global__ __launch_bounds__(SCAN_B) void k_scan() {
    int b = blockIdx.x, t = threadIdx.x;
    int gid = b * SCAN_B + t;
    unsigned long long pk = (gid < NN) ? g_pack[gid] : 0ull;
    int v = (int)(pk >> 40);

    int lane = t & 31, wid = t >> 5;
    int incl = v;
    #pragma unroll
    for (int o = 1; o < 32; o <<= 1) {
        int u = __shfl_up_sync(0xffffffffu, incl, o);
        if (lane >= o) incl += u;
    }
    __shared__ int ws[32];
    if (lane == 31) ws[wid] = incl;
    __syncthreads();
    if (wid == 0) {
        int s = ws[lane];
        #pragma unroll
        for (int o = 1; o < 32; o <<= 1) {
            int u = __shfl_up_sync(0xffffffffu, s, o);
            if (lane >= o) s += u;
        }
        ws[lane] = s;
    }
    __syncthreads();
    if (wid > 0) incl += ws[wid - 1];
    int total = ws[31];

    if (t == 0)
        atomicExch((unsigned long long*)&g_sstat[b],
                   (1ull << 63) | (unsigned long long)total);

    __shared__ int boff_s;
    if (wid == 0) {
        int run = 0;
        for (int i = lane; i < b; i += 32) {
            unsigned long long s;
            do { s = g_sstat[i]; } while (!(s >> 63));
            run += (int)(s & 0x7FFFFFFFFFFFFFFFull);
        }
        #pragma unroll
        for (int o = 16; o > 0; o >>= 1)
            run += __shfl_xor_sync(0xffffffffu, run, o);
        if (lane == 0) boff_s = run;
    }
    __syncthreads();

    if (gid < NN) {
        g_rowptr[gid] = boff_s + incl - v;
        g_pack[gid]   = 0ull;                // self-clean for next replay
        float degw = (float)(pk & 0xFFFFFFFFFFull) * (1.0f / 4294967296.0f);
        g_dinv[gid] = rsqrtf(degw + 1.0f);
    }
    if (gid == NN) g_rowptr[NN] = boff_s + incl;
}

// ------- CSR fill: 4 edges/thread, no atomics, payload = bare fp16(w) ----------
__global__ void k_fill(const float* __restrict__ w) {
    int t = blockIdx.x * blockDim.x + threadIdx.x;
    if (t < NBLK) g_sstat[t] = 0ull;     // self-clean scan status
    int e0 = t * 4;
    if (e0 >= NE) return;
    int4 sd0 = ((const int4*)g_sd)[(e0 >> 1)];
    int4 sd1 = ((const int4*)g_sd)[(e0 >> 1) + 1];
    ushort4 rk = *(const ushort4*)&g_rank[e0];
    float4 wv = *(const float4*)&w[e0];
    int ss[4] = {sd0.x, sd0.z, sd1.x, sd1.z};
    int dd[4] = {sd0.y, sd0.w, sd1.y, sd1.w};
    unsigned short rr[4] = {rk.x, rk.y, rk.z, rk.w};
    float wa[4] = {wv.x, wv.y, wv.z, wv.w};
    #pragma unroll
    for (int j = 0; j < 4; j++) {
        int pos = g_rowptr[dd[j]] + (int)rr[j];
        unsigned hb = (unsigned)__half_as_ushort(__float2half(wa[j]));
        g_edge[pos] = ((unsigned)ss[j] << 15) | (hb & 0x7FFFu);
    }
}

// ---------------- mma / unpack helpers ----------------
__device__ __forceinline__ void mma16816bf(float* d,
                                           unsigned a0, unsigned a1, unsigned a2, unsigned a3,
                                           unsigned b0, unsigned b1) {
    asm volatile(
        "mma.sync.aligned.m16n8k16.row.col.f32.bf16.bf16.f32 "
        "{%0,%1,%2,%3}, {%4,%5,%6,%7}, {%8,%9}, {%0,%1,%2,%3};"
        : "+f"(d[0]), "+f"(d[1]), "+f"(d[2]), "+f"(d[3])
        : "r"(a0), "r"(a1), "r"(a2), "r"(a3), "r"(b0), "r"(b1));
}
__device__ __forceinline__ void mma16816h(float* d,
                                          unsigned a0, unsigned a1, unsigned a2, unsigned a3,
                                          unsigned b0, unsigned b1) {
    asm volatile(
        "mma.sync.aligned.m16n8k16.row.col.f32.f16.f16.f32 "
        "{%0,%1,%2,%3}, {%4,%5,%6,%7}, {%8,%9}, {%0,%1,%2,%3};"
        : "+f"(d[0]), "+f"(d[1]), "+f"(d[2]), "+f"(d[3])
        : "r"(a0), "r"(a1), "r"(a2), "r"(a3), "r"(b0), "r"(b1));
}
__device__ __forceinline__ void fma8(float* acc, uint4 v, float n) {
    float2 f0 = __half22float2(*(__half2*)&v.x);
    float2 f1 = __half22float2(*(__half2*)&v.y);
    float2 f2 = __half22float2(*(__half2*)&v.z);
    float2 f3 = __half22float2(*(__half2*)&v.w);
    acc[0] = fmaf(n, f0.x, acc[0]); acc[1] = fmaf(n, f0.y, acc[1]);
    acc[2] = fmaf(n, f1.x, acc[2]); acc[3] = fmaf(n, f1.y, acc[3]);
    acc[4] = fmaf(n, f2.x, acc[4]); acc[5] = fmaf(n, f2.y, acc[5]);
    acc[6] = fmaf(n, f3.x, acc[6]); acc[7] = fmaf(n, f3.y, acc[7]);
}
__device__ __forceinline__ float edge_norm(unsigned u) {
    return __half2float(__ushort_as_half((unsigned short)(u & 0x7FFFu)));
}

// ---------- GEMM1: 512 thr, 16 warps x m16, dinv-scaled fp16 output -----------
__global__ __launch_bounds__(512) void k_gemm1(const float* __restrict__ x,
                                               const float* __restrict__ W1) {
    extern __shared__ __nv_bfloat16 sh[];
    __nv_bfloat16* As = sh;                  // [GR][APAD]
    __nv_bfloat16* Ws = sh + GR * APAD;      // [NH][APAD]
    int tid = threadIdx.x;
    int row0 = blockIdx.x * GR;

    const float4* W4 = (const float4*)W1;
    for (int i = tid; i < (NF * NH) / 4; i += 512) {
        int idx = i * 4;
        int k = idx / NH;
        int n = idx % NH;
        float4 w = W4[i];
        Ws[(n + 0) * APAD + k] = __float2bfloat16(w.x);
        Ws[(n + 1) * APAD + k] = __float2bfloat16(w.y);
        Ws[(n + 2) * APAD + k] = __float2bfloat16(w.z);
        Ws[(n + 3) * APAD + k] = __float2bfloat16(w.w);
    }

    const float4* x4 = (const float4*)x;
    #pragma unroll
    for (int it = 0; it < GR * 32 / 512; it++) {
        int i  = tid + 512 * it;
        int r  = i >> 5;
        int c4 = i & 31;
        int gr = row0 + r;
        float4 v = (gr < NN) ? x4[(size_t)gr * 32 + c4] : make_float4(0.f, 0.f, 0.f, 0.f);
        __nv_bfloat162 p0 = __float22bfloat162_rn(make_float2(v.x, v.y));
        __nv_bfloat162 p1 = __float22bfloat162_rn(make_float2(v.z, v.w));
        *(__nv_bfloat162*)&As[r * APAD + c4 * 4]     = p0;
        *(__nv_bfloat162*)&As[r * APAD + c4 * 4 + 2] = p1;
    }
    __syncthreads();

    int w    = tid >> 5;
    int lane = tid & 31;
    int g    = lane >> 2;
    int tg   = lane & 3;
    int mrow0 = w * 16;

    float acc[8][4];
    #pragma unroll
    for (int nt = 0; nt < 8; nt++)
        #pragma unroll
        for (int c = 0; c < 4; c++) acc[nt][c] = 0.f;

    #pragma unroll
    for (int ks = 0; ks < NF / 16; ks++) {
        int k0 = ks * 16;
        unsigned a0 = *(const unsigned*)&As[(mrow0 + g)     * APAD + k0 + tg * 2];
        unsigned a1 = *(const unsigned*)&As[(mrow0 + g + 8) * APAD + k0 + tg * 2];
        unsigned a2 = *(const unsigned*)&As[(mrow0 + g)     * APAD + k0 + tg * 2 + 8];
        unsigned a3 = *(const unsigned*)&As[(mrow0 + g + 8) * APAD + k0 + tg * 2 + 8];
        #pragma unroll
        for (int nt = 0; nt < 8; nt++) {
            unsigned b0 = *(const unsigned*)&Ws[(nt * 8 + g) * APAD + k0 + tg * 2];
            unsigned b1 = *(const unsigned*)&Ws[(nt * 8 + g) * APAD + k0 + tg * 2 + 8];
            mma16816bf(acc[nt], a0, a1, a2, a3, b0, b1);
        }
    }

    int rA = row0 + mrow0 + g;
    int rB = rA + 8;
    float dA = (rA < NN) ? g_dinv[rA] : 0.f;
    float dB = (rB < NN) ? g_dinv[rB] : 0.f;
    #pragma unroll
    for (int nt = 0; nt < 8; nt++) {
        int colh2 = nt * 4 + tg;
        if (rA < NN)
            g_h1h[(size_t)rA * 32 + colh2] =
                __floats2half2_rn(dA * acc[nt][0], dA * acc[nt][1]);
        if (rB < NN)
            g_h1h[(size_t)rB * 32 + colh2] =
                __floats2half2_rn(dB * acc[nt][2], dB * acc[nt][3]);
    }
}

// ---------------- AGG1: 8-lane-group vector gather + bias + relu ----------------
__global__ __launch_bounds__(256) void k_agg1(const float* __restrict__ b1) {
    int node = (blockIdx.x * blockDim.x + threadIdx.x) >> 5;
    int lane = threadIdx.x & 31;
    if (node >= NN) return;
    int beg = g_rowptr[node];
    int end = g_rowptr[node + 1];
    float di = g_dinv[node];
    int g8 = lane >> 3;
    int fc = lane & 7;

    const uint4* h4 = (const uint4*)g_h1h;
    float acc[8];
    #pragma unroll
    for (int j = 0; j < 8; j++) acc[j] = 0.f;
    if (g8 == 0) {
        uint4 sv = h4[(size_t)node * 8 + fc];
        fma8(acc, sv, 1.0f);   // self: h1'[d] (already dinv-scaled); final *di gives di^2*h1
    }

    int e = beg;
    for (; e + 7 < end; e += 8) {
        unsigned u0 = g_edge[e + g8];
        unsigned u1 = g_edge[e + 4 + g8];
        int s0 = (int)(u0 >> 15), s1 = (int)(u1 >> 15);
        uint4 v0 = h4[(size_t)s0 * 8 + fc];
        uint4 v1 = h4[(size_t)s1 * 8 + fc];
        fma8(acc, v0, edge_norm(u0));
        fma8(acc, v1, edge_norm(u1));
    }
    for (; e < end; e += 4) {
        int ee = e + g8;
        float n = 0.f;
        int s = 0;
        if (ee < end) {
            unsigned u = g_edge[ee];
            s = (int)(u >> 15);
            n = edge_norm(u);
        }
        uint4 v = h4[(size_t)s * 8 + fc];
        fma8(acc, v, n);
    }

    #pragma unroll
    for (int j = 0; j < 8; j++) {
        acc[j] += __shfl_xor_sync(0xffffffffu, acc[j], 8);
        acc[j] += __shfl_xor_sync(0xffffffffu, acc[j], 16);
    }

    if (g8 == 0) {
        float4 bA = *(const float4*)&b1[fc * 8];
        float4 bB = *(const float4*)&b1[fc * 8 + 4];
        float r0 = fmaxf(fmaf(di, acc[0], bA.x), 0.f);
        float r1 = fmaxf(fmaf(di, acc[1], bA.y), 0.f);
        float r2 = fmaxf(fmaf(di, acc[2], bA.z), 0.f);
        float r3 = fmaxf(fmaf(di, acc[3], bA.w), 0.f);
        float r4 = fmaxf(fmaf(di, acc[4], bB.x), 0.f);
        float r5 = fmaxf(fmaf(di, acc[5], bB.y), 0.f);
        float r6 = fmaxf(fmaf(di, acc[6], bB.z), 0.f);
        float r7 = fmaxf(fmaf(di, acc[7], bB.w), 0.f);
        uint4 st;
        __half2 h0 = __floats2half2_rn(r0, r1);
        __half2 h1 = __floats2half2_rn(r2, r3);
        __half2 h2 = __floats2half2_rn(r4, r5);
        __half2 h3 = __floats2half2_rn(r6, r7);
        st.x = *(unsigned*)&h0; st.y = *(unsigned*)&h1;
        st.z = *(unsigned*)&h2; st.w = *(unsigned*)&h3;
        ((uint4*)g_a1h)[(size_t)node * 8 + fc] = st;
    }
}

// -------- GEMM2: h2' = dinv*(a1 @ W2), fp16 mma, padded fp16 rows --------------
__global__ __launch_bounds__(256) void k_gemm2(const float* __restrict__ W2) {
    extern __shared__ __half sh2[];
    __half* As = sh2;                    // [G2R][A2PAD]
    __half* Ws = sh2 + G2R * A2PAD;      // [NC][A2PAD]
    int tid = threadIdx.x;
    int row0 = blockIdx.x * G2R;

    for (int i = tid; i < NH * NC; i += 256) {
        int k = i / NC, n = i % NC;
        Ws[n * A2PAD + k] = __float2half(W2[i]);
    }
    const uint4* a4 = (const uint4*)g_a1h;
    #pragma unroll
    for (int it = 0; it < G2R * 8 / 256; it++) {
        int i = tid + 256 * it;
        int r = i >> 3;
        int c = i & 7;
        int gr = row0 + r;
        uint4 v = (gr < NN) ? a4[(size_t)gr * 8 + c] : make_uint4(0u, 0u, 0u, 0u);
        *(uint4*)&As[r * A2PAD + c * 8] = v;
    }
    __syncthreads();

    int w    = tid >> 5;
    int lane = tid & 31;
    int g    = lane >> 2;
    int tg   = lane & 3;
    int mrow0 = w * 16;

    float acc[5][4];
    #pragma unroll
    for (int nt = 0; nt < 5; nt++)
        #pragma unroll
        for (int c = 0; c < 4; c++) acc[nt][c] = 0.f;

    #pragma unroll
    for (int ks = 0; ks < NH / 16; ks++) {
        int k0 = ks * 16;
        unsigned a0 = *(const unsigned*)&As[(mrow0 + g)     * A2PAD + k0 + tg * 2];
        unsigned a1 = *(const unsigned*)&As[(mrow0 + g + 8) * A2PAD + k0 + tg * 2];
        unsigned a2 = *(const unsigned*)&As[(mrow0 + g)     * A2PAD + k0 + tg * 2 + 8];
        unsigned a3 = *(const unsigned*)&As[(mrow0 + g + 8) * A2PAD + k0 + tg * 2 + 8];
        #pragma unroll
        for (int nt = 0; nt < 5; nt++) {
            unsigned b0 = *(const unsigned*)&Ws[(nt * 8 + g) * A2PAD + k0 + tg * 2];
            unsigned b1 = *(const unsigned*)&Ws[(nt * 8 + g) * A2PAD + k0 + tg * 2 + 8];
            mma16816h(acc[nt], a0, a1, a2, a3, b0, b1);
        }
    }

    int rA = row0 + mrow0 + g;
    int rB = rA + 8;
    float dA = (rA < NN) ? g_dinv[rA] : 0.f;
    float dB = (rB < NN) ? g_dinv[rB] : 0.f;
    #pragma unroll
    for (int nt = 0; nt < 5; nt++) {
        int col = nt * 8 + tg * 2;
        if (rA < NN)
            *(__half2*)&g_h2h[(size_t)rA * H2S + col] =
                __floats2half2_rn(dA * acc[nt][0], dA * acc[nt][1]);
        if (rB < NN)
            *(__half2*)&g_h2h[(size_t)rB * H2S + col] =
                __floats2half2_rn(dB * acc[nt][2], dB * acc[nt][3]);
    }
}

// ---------------- AGG2: 8-lane-group vector gather + bias + log_softmax ---------
__global__ __launch_bounds__(256) void k_agg2(const float* __restrict__ b2,
                                              float* __restrict__ out) {
    int node = (blockIdx.x * blockDim.x + threadIdx.x) >> 5;
    int lane = threadIdx.x & 31;
    if (node >= NN) return;
    int beg = g_rowptr[node];
    int end = g_rowptr[node + 1];
    float di = g_dinv[node];
    int g8 = lane >> 3;
    int fc = lane & 7;

    const uint4* h4 = (const uint4*)g_h2h;
    float acc[8];
    #pragma unroll
    for (int j = 0; j < 8; j++) acc[j] = 0.f;
    if (g8 == 0) {
        uint4 sv = h4[(size_t)node * 8 + fc];
        fma8(acc, sv, 1.0f);   // self: h2'[d] (already dinv-scaled)
    }

    int e = beg;
    for (; e + 7 < end; e += 8) {
        unsigned u0 = g_edge[e + g8];
        unsigned u1 = g_edge[e + 4 + g8];
        int s0 = (int)(u0 >> 15), s1 = (int)(u1 >> 15);
        uint4 v0 = h4[(size_t)s0 * 8 + fc];
        uint4 v1 = h4[(size_t)s1 * 8 + fc];
        fma8(acc, v0, edge_norm(u0));
        fma8(acc, v1, edge_norm(u1));
    }
    for (; e < end; e += 4) {
        int ee = e + g8;
        float n = 0.f;
        int s = 0;
        if (ee < end) {
            unsigned u = g_edge[ee];
            s = (int)(u >> 15);
            n = edge_norm(u);
        }
        uint4 v = h4[(size_t)s * 8 + fc];
        fma8(acc, v, n);
    }

    #pragma unroll
    for (int j = 0; j < 8; j++) {
        acc[j] += __shfl_xor_sync(0xffffffffu, acc[j], 8);
        acc[j] += __shfl_xor_sync(0xffffffffu, acc[j], 16);
    }

    float v[8];
    float mloc = -1e30f;
    if (fc < 5) {
        float4 bA = *(const float4*)&b2[fc * 8];
        float4 bB = *(const float4*)&b2[fc * 8 + 4];
        v[0] = fmaf(di, acc[0], bA.x); v[1] = fmaf(di, acc[1], bA.y);
        v[2] = fmaf(di, acc[2], bA.z); v[3] = fmaf(di, acc[3], bA.w);
        v[4] = fmaf(di, acc[4], bB.x); v[5] = fmaf(di, acc[5], bB.y);
        v[6] = fmaf(di, acc[6], bB.z); v[7] = fmaf(di, acc[7], bB.w);
        #pragma unroll
        for (int j = 0; j < 8; j++) mloc = fmaxf(mloc, v[j]);
    }
    #pragma unroll
    for (int off = 16; off > 0; off >>= 1)
        mloc = fmaxf(mloc, __shfl_xor_sync(0xffffffffu, mloc, off));

    float sloc = 0.f;
    if (fc < 5 && g8 == 0) {
        #pragma unroll
        for (int j = 0; j < 8; j++) sloc += __expf(v[j] - mloc);
    }
    #pragma unroll
    for (int off = 16; off > 0; off >>= 1)
        sloc += __shfl_xor_sync(0xffffffffu, sloc, off);
    float lse = mloc + __logf(sloc);

    if (fc < 5 && g8 == 0) {
        float* o = out + (size_t)node * NC + fc * 8;
        *(float4*)o       = make_float4(v[0] - lse, v[1] - lse, v[2] - lse, v[3] - lse);
        *(float4*)(o + 4) = make_float4(v[4] - lse, v[5] - lse, v[6] - lse, v[7] - lse);
    }
}

// -------- launcher (fork after scan: gemm1 overlaps fill) ----------------------
extern "C" void kernel_launch(void* const* d_in, const int* in_sizes, int n_in,
                              void* d_out, int out_size) {
    const float* x  = (const float*)d_in[0];
    const void*  ei = d_in[1];
    const float* ew = (const float*)d_in[2];
    const float* W1 = (const float*)d_in[3];
    const float* b1 = (const float*)d_in[4];
    const float* W2 = (const float*)d_in[5];
    const float* b2 = (const float*)d_in[6];
    float* out = (float*)d_out;

    const int E4B = (NE / 4 + 255) / 256;   // 1563
    const int G1B = (NN + GR - 1) / GR;     // 391
    const int G2B = (NN + G2R - 1) / G2R;   // 782
    const int AB  = (NN * 32 + 255) / 256;  // 12500

    static cudaStream_t sA = nullptr;
    static cudaEvent_t evScan = nullptr, evG1 = nullptr;
    if (sA == nullptr) {
        cudaStreamCreateWithFlags(&sA, cudaStreamNonBlocking);
        cudaEventCreateWithFlags(&evScan, cudaEventDisableTiming);
        cudaEventCreateWithFlags(&evG1, cudaEventDisableTiming);
        cudaFuncSetAttribute(k_gemm1, cudaFuncAttributeMaxDynamicSharedMemorySize, G1_SMEM);
        cudaFuncSetAttribute(k_gemm2, cudaFuncAttributeMaxDynamicSharedMemorySize, G2_SMEM);
    }

    // main stream: decode + scan (produces dinv)
    k_decode_deg<<<E4B, 256>>>(ei, ew);
    k_scan<<<NBLK, SCAN_B>>>();
    cudaEventRecord(evScan, 0);

    // side stream: gemm1 (needs dinv) overlaps fill
    cudaStreamWaitEvent(sA, evScan, 0);
    k_gemm1<<<G1B, 512, G1_SMEM, sA>>>(x, W1);
    cudaEventRecord(evG1, sA);

    // main stream: CSR fill
    k_fill<<<E4B, 256>>>(ew);

    // join: agg1 needs both h1 (sA) and CSR (stream 0)
    cudaStreamWaitEvent(0, evG1, 0);
    k_agg1<<<AB, 256>>>(b1);
    k_gemm2<<<G2B, 256, G2_SMEM>>>(W2);
    k_agg2<<<AB, 256>>>(b2, out);
}